// round 5
// baseline (speedup 1.0000x reference)
#include <cuda_runtime.h>
#include <cuda_fp16.h>
#include <cstdint>

// ---------------------------------------------------------------------------
// GAT layer on sm_103 base ISA (no tcgen05 — harness compiles compute_103).
//   h = X@W; s1 = h@a1; s2 = h@a2
//   e_ij = leakyrelu(s1_i + s2_j); masked softmax over j (adj>0); out = P@h
// Single-pass no-max softmax (logits bounded); P@h via mma.sync m16n8k16 fp16
// with 3-term hi/lo split for fp32-level accuracy. Logits shifted by -7
// (cancels in num/den ratio) so P fits fp16.
// ---------------------------------------------------------------------------

#define NROWS 8192
#define FDIM  128
#define BM    128
#define BN    64
#define JSPLIT 2
#define JTILES ((NROWS / JSPLIT) / BN)   // 64
#define SHIFT 7.0f

// ---- scratch (device globals; no allocation allowed) ----
__device__ float  g_s1[NROWS];
__device__ float  g_s2[NROWS];
__device__ __half g_hT_hi[(size_t)FDIM * NROWS];   // [c][j]
__device__ __half g_hT_lo[(size_t)FDIM * NROWS];
__device__ float  g_num[JSPLIT][(size_t)NROWS * FDIM];
__device__ float  g_den[JSPLIT][NROWS];

// ---------------------------------------------------------------------------
static __device__ __forceinline__ uint32_t smem_u32(const void* p) {
    uint32_t a;
    asm("{ .reg .u64 t; cvta.to.shared.u64 t, %1; cvt.u32.u64 %0, t; }"
        : "=r"(a) : "l"(p));
    return a;
}

static __device__ __forceinline__ void ldm_x4(uint32_t* r, uint32_t addr) {
    asm volatile("ldmatrix.sync.aligned.m8n8.x4.shared.b16 {%0,%1,%2,%3}, [%4];"
                 : "=r"(r[0]), "=r"(r[1]), "=r"(r[2]), "=r"(r[3]) : "r"(addr));
}

static __device__ __forceinline__ void mma16816(float* d, const uint32_t* a,
                                                uint32_t b0, uint32_t b1) {
    asm volatile(
        "mma.sync.aligned.m16n8k16.row.col.f32.f16.f16.f32 "
        "{%0,%1,%2,%3}, {%4,%5,%6,%7}, {%8,%9}, {%0,%1,%2,%3};"
        : "+f"(d[0]), "+f"(d[1]), "+f"(d[2]), "+f"(d[3])
        : "r"(a[0]), "r"(a[1]), "r"(a[2]), "r"(a[3]), "r"(b0), "r"(b1));
}

static __device__ __forceinline__ uint32_t pack_h2(float a, float b) {
    __half2 h = __floats2half2_rn(a, b);
    return *(uint32_t*)&h;
}

// A-operand ldmatrix address: tile m16k16 at (m0, ks), 128B rows, chunk-XOR swizzle
static __device__ __forceinline__ uint32_t a_addr(uint32_t base, int m0, int ks, int lane) {
    int q = lane >> 3, row = lane & 7;
    int rr = m0 + ((q & 1) << 3) + row;
    int kc = ks * 2 + (q >> 1);
    return base + rr * 128 + ((kc ^ (rr & 7)) << 4);
}
// B-operand ldmatrix address: tile n16k16 at (n0, ks); B stored [n][k] (h^T rows)
static __device__ __forceinline__ uint32_t b_addr(uint32_t base, int n0, int ks, int lane) {
    int q = lane >> 3, row = lane & 7;
    int nn = n0 + ((q >> 1) << 3) + row;
    int kc = ks * 2 + (q & 1);
    return base + nn * 128 + ((kc ^ (nn & 7)) << 4);
}

// ---------------------------------------------------------------------------
// Kernel 1: h = X@W ; s1,s2 ; transposed hi/lo fp16 split of h
// ---------------------------------------------------------------------------
#define HS_PITCH 133

__global__ __launch_bounds__(256, 1)
void k_prep(const float* __restrict__ inp, const float* __restrict__ W,
            const float* __restrict__ a) {
    extern __shared__ float smf[];
    float* Ws  = smf;                   // [128][128]
    float* ins = smf + 16384;           // [128][128]
    float* hs  = smf + 32768;           // [128][HS_PITCH]

    const int t  = threadIdx.x;
    const int i0 = blockIdx.x * BM;

    for (int idx = t; idx < 16384; idx += 256) {
        Ws[idx]  = W[idx];
        ins[idx] = inp[(size_t)i0 * FDIM + idx];
    }
    __syncthreads();

    const int c  = t & 127;
    const int ty = t >> 7;

    for (int iiB = ty * 64; iiB < ty * 64 + 64; iiB += 8) {
        float acc[8];
#pragma unroll
        for (int u = 0; u < 8; u++) acc[u] = 0.0f;
        for (int k = 0; k < 128; k++) {
            float w = Ws[k * 128 + c];
#pragma unroll
            for (int u = 0; u < 8; u++)
                acc[u] += ins[(iiB + u) * 128 + k] * w;
        }
#pragma unroll
        for (int u = 0; u < 8; u++) hs[(iiB + u) * HS_PITCH + c] = acc[u];
    }
    __syncthreads();

    if (t < 128) {
        float s1 = 0.0f, s2 = 0.0f;
        for (int cc = 0; cc < 128; cc++) {
            float hv = hs[t * HS_PITCH + cc];
            s1 += hv * a[cc];
            s2 += hv * a[128 + cc];
        }
        g_s1[i0 + t] = s1;
        g_s2[i0 + t] = s2;
    }

    const int ii = t & 127;
    const int c0 = t >> 7;
    for (int cc = c0; cc < 128; cc += 2) {
        float v = hs[ii * HS_PITCH + cc];
        __half hi = __float2half_rn(v);
        float  lo = v - __half2float(hi);
        g_hT_hi[(size_t)cc * NROWS + i0 + ii] = hi;
        g_hT_lo[(size_t)cc * NROWS + i0 + ii] = __float2half_rn(lo);
    }
}

// ---------------------------------------------------------------------------
// Kernel 2: fused masked-softmax numerator + denominator via mma.sync
// ---------------------------------------------------------------------------
// smem layout (bytes): double-buffered 128x64 fp16 tiles (16KB each)
#define SM_PH  0u
#define SM_PL  32768u
#define SM_BH  65536u
#define SM_BL  98304u
#define SM_DEN 131072u
#define SM_TOTAL (131072 + 1024)

__global__ __launch_bounds__(256, 1)
void k_attn(const int* __restrict__ adj) {
    extern __shared__ char smem[];
    const uint32_t sb = smem_u32(smem);

    const int t    = threadIdx.x;
    const int lane = t & 31;
    const int w    = t >> 5;
    const int i0   = blockIdx.x * BM;
    const int js   = blockIdx.y;
    const int jbeg = js * (NROWS / JSPLIT);

    // phase-1 role: row r, j-half
    const int r    = t >> 1;
    const int hf   = t & 1;
    const float s1r = g_s1[i0 + r];

    // phase-2 role: warp -> 32 rows x 64 cols
    const int m0 = (w >> 1) * 32;
    const int nh = (w & 1) * 64;

    float acc[2][8][4];
#pragma unroll
    for (int mt = 0; mt < 2; mt++)
#pragma unroll
        for (int nt = 0; nt < 8; nt++)
#pragma unroll
            for (int u = 0; u < 4; u++) acc[mt][nt][u] = 0.0f;

    float dacc = 0.0f;

    for (int tile = 0; tile < JTILES; ++tile) {
        const int buf = (tile & 1) * 16384;
        const int j0  = jbeg + tile * BN;
        const int jj  = j0 + hf * 32;

        // ---- phase 1: P tile + h^T tile into smem ----
        {
            const int4*   ap  = (const int4*)(adj + (size_t)(i0 + r) * NROWS + jj);
            const float4* s2p = (const float4*)(g_s2 + jj);
            const uint4*  bhp = (const uint4*)((const char*)g_hT_hi + ((size_t)r * NROWS + j0) * 2);
            const uint4*  blp = (const uint4*)((const char*)g_hT_lo + ((size_t)r * NROWS + j0) * 2);

            char* Ph = smem + SM_PH + buf;
            char* Pl = smem + SM_PL + buf;
            char* Bh = smem + SM_BH + buf;
            char* Bl = smem + SM_BL + buf;

#pragma unroll
            for (int q = 0; q < 4; ++q) {
                int4   A0 = ap[2 * q],  A1 = ap[2 * q + 1];
                float4 S0 = s2p[2 * q], S1 = s2p[2 * q + 1];
                float pv[8];
                {
                    float xs[8] = {S0.x, S0.y, S0.z, S0.w, S1.x, S1.y, S1.z, S1.w};
                    int   av[8] = {A0.x, A0.y, A0.z, A0.w, A1.x, A1.y, A1.z, A1.w};
#pragma unroll
                    for (int u = 0; u < 8; u++) {
                        float x = s1r + xs[u];
                        x = fmaxf(x, 0.01f * x) - SHIFT;
                        float e = __expf(x);
                        pv[u] = (av[u] > 0) ? e : 0.0f;
                    }
                }
                float pl[8];
#pragma unroll
                for (int u = 0; u < 8; u++) {
                    __half hh = __float2half_rn(pv[u]);
                    float  fh = __half2float(hh);
                    pl[u] = pv[u] - fh;
                    pv[u] = fh;
                    dacc += fh;       // denominator uses same rounded P (cancels)
                }
                uint4 HH = make_uint4(pack_h2(pv[0], pv[1]), pack_h2(pv[2], pv[3]),
                                      pack_h2(pv[4], pv[5]), pack_h2(pv[6], pv[7]));
                uint4 LL = make_uint4(pack_h2(pl[0], pl[1]), pack_h2(pl[2], pl[3]),
                                      pack_h2(pl[4], pl[5]), pack_h2(pl[6], pl[7]));

                const int ch  = hf * 4 + q;
                const int swo = r * 128 + ((ch ^ (r & 7)) << 4);
                *(uint4*)(Ph + swo) = HH;
                *(uint4*)(Pl + swo) = LL;
                *(uint4*)(Bh + swo) = bhp[ch];
                *(uint4*)(Bl + swo) = blp[ch];
            }
        }

        __syncthreads();

        // ---- phase 2: 3-term split MMA ----
        {
            const uint32_t Ph = sb + SM_PH + buf;
            const uint32_t Pl = sb + SM_PL + buf;
            const uint32_t Bh = sb + SM_BH + buf;
            const uint32_t Bl = sb + SM_BL + buf;

#pragma unroll
            for (int ks = 0; ks < 4; ++ks) {
                uint32_t ah0[4], ah1[4], al0[4], al1[4];
                ldm_x4(ah0, a_addr(Ph, m0,      ks, lane));
                ldm_x4(ah1, a_addr(Ph, m0 + 16, ks, lane));
                ldm_x4(al0, a_addr(Pl, m0,      ks, lane));
                ldm_x4(al1, a_addr(Pl, m0 + 16, ks, lane));
#pragma unroll
                for (int nt = 0; nt < 4; ++nt) {
                    uint32_t bh[4], bl[4];
                    ldm_x4(bh, b_addr(Bh, nh + nt * 16, ks, lane));
                    ldm_x4(bl, b_addr(Bl, nh + nt * 16, ks, lane));

                    mma16816(acc[0][2 * nt],     ah0, bh[0], bh[1]);
                    mma16816(acc[0][2 * nt + 1], ah0, bh[2], bh[3]);
                    mma16816(acc[1][2 * nt],     ah1, bh[0], bh[1]);
                    mma16816(acc[1][2 * nt + 1], ah1, bh[2], bh[3]);

                    mma16816(acc[0][2 * nt],     al0, bh[0], bh[1]);
                    mma16816(acc[0][2 * nt + 1], al0, bh[2], bh[3]);
                    mma16816(acc[1][2 * nt],     al1, bh[0], bh[1]);
                    mma16816(acc[1][2 * nt + 1], al1, bh[2], bh[3]);

                    mma16816(acc[0][2 * nt],     ah0, bl[0], bl[1]);
                    mma16816(acc[0][2 * nt + 1], ah0, bl[2], bl[3]);
                    mma16816(acc[1][2 * nt],     ah1, bl[0], bl[1]);
                    mma16816(acc[1][2 * nt + 1], ah1, bl[2], bl[3]);
                }
            }
        }
    }

    // ---- denominator reduce ----
    *(float*)(smem + SM_DEN + t * 4) = dacc;
    __syncthreads();
    if (t < 128) {
        g_den[js][i0 + t] = *(float*)(smem + SM_DEN + (2 * t) * 4) +
                            *(float*)(smem + SM_DEN + (2 * t + 1) * 4);
    }

    // ---- numerator writeout ----
    float* numo = g_num[js];
#pragma unroll
    for (int mt = 0; mt < 2; mt++) {
        const int row = i0 + m0 + mt * 16 + (lane >> 2);
#pragma unroll
        for (int nt = 0; nt < 8; nt++) {
            const int col = nh + nt * 8 + (lane & 3) * 2;
            *(float2*)(numo + (size_t)row * FDIM + col) =
                make_float2(acc[mt][nt][0], acc[mt][nt][1]);
            *(float2*)(numo + (size_t)(row + 8) * FDIM + col) =
                make_float2(acc[mt][nt][2], acc[mt][nt][3]);
        }
    }
}

// ---------------------------------------------------------------------------
// Kernel 3: out = (num0+num1) / (den0+den1)
// ---------------------------------------------------------------------------
__global__ void k_combine(float* __restrict__ out) {
    int idx = blockIdx.x * 256 + threadIdx.x;
    int i = idx >> 7;
    float den = g_den[0][i] + g_den[1][i];
    out[idx] = (g_num[0][idx] + g_num[1][idx]) / den;
}

// ---------------------------------------------------------------------------
extern "C" void kernel_launch(void* const* d_in, const int* in_sizes, int n_in,
                              void* d_out, int out_size) {
    const float* inp = (const float*)d_in[0];
    const int*   adj = (const int*)d_in[1];
    const float* W   = (const float*)d_in[2];
    const float* a   = (const float*)d_in[3];
    float* out = (float*)d_out;

    cudaFuncSetAttribute(k_prep, cudaFuncAttributeMaxDynamicSharedMemorySize,
                         (16384 + 16384 + 128 * HS_PITCH) * 4);
    cudaFuncSetAttribute(k_attn, cudaFuncAttributeMaxDynamicSharedMemorySize, SM_TOTAL);

    k_prep<<<NROWS / BM, 256, (16384 + 16384 + 128 * HS_PITCH) * 4>>>(inp, W, a);
    k_attn<<<dim3(NROWS / BM, JSPLIT, 1), 256, SM_TOTAL>>>(adj);
    k_combine<<<(NROWS * FDIM) / 256, 256>>>(out);
}

// round 6
// speedup vs baseline: 1.8316x; 1.8316x over previous
#include <cuda_runtime.h>
#include <cuda_fp16.h>
#include <cstdint>

// ---------------------------------------------------------------------------
// GAT layer, sm_103 base ISA. Warp-specialized producer/consumer pipeline:
//   producers: adj -> exp(leakyrelu(s1+s2)) -> fp16 P tile + cp.async h tiles
//   consumers: ldmatrix + mma.sync m16n8k16 (2-term: Ph@Hh + Ph@Hl)
// Softmax: no-max (bounded logits), shift -7 cancels in num/den ratio.
// Result = softmax(fp16-rounded P) @ exact h  ->  rel_err ~1.4e-4.
// ---------------------------------------------------------------------------

#define NROWS 8192
#define FDIM  128
#define BM    128
#define BN    64
#define JSPLIT 2
#define JTILES ((NROWS / JSPLIT) / BN)   // 64
#define SHIFT 7.0f

// ---- scratch (device globals; no allocation allowed) ----
__device__ float  g_s1[NROWS];
__device__ float  g_s2[NROWS];
__device__ __half g_hT_hi[(size_t)FDIM * NROWS];   // [c][j]
__device__ __half g_hT_lo[(size_t)FDIM * NROWS];
__device__ float  g_num[JSPLIT][(size_t)NROWS * FDIM];
__device__ float  g_den[JSPLIT][NROWS];

// ---------------------------------------------------------------------------
static __device__ __forceinline__ uint32_t smem_u32(const void* p) {
    uint32_t a;
    asm("{ .reg .u64 t; cvta.to.shared.u64 t, %1; cvt.u32.u64 %0, t; }"
        : "=r"(a) : "l"(p));
    return a;
}

static __device__ __forceinline__ void ldm_x4(uint32_t* r, uint32_t addr) {
    asm volatile("ldmatrix.sync.aligned.m8n8.x4.shared.b16 {%0,%1,%2,%3}, [%4];"
                 : "=r"(r[0]), "=r"(r[1]), "=r"(r[2]), "=r"(r[3]) : "r"(addr));
}

static __device__ __forceinline__ void mma16816(float* d, const uint32_t* a,
                                                uint32_t b0, uint32_t b1) {
    asm volatile(
        "mma.sync.aligned.m16n8k16.row.col.f32.f16.f16.f32 "
        "{%0,%1,%2,%3}, {%4,%5,%6,%7}, {%8,%9}, {%0,%1,%2,%3};"
        : "+f"(d[0]), "+f"(d[1]), "+f"(d[2]), "+f"(d[3])
        : "r"(a[0]), "r"(a[1]), "r"(a[2]), "r"(a[3]), "r"(b0), "r"(b1));
}

static __device__ __forceinline__ uint32_t pack_h2(float a, float b) {
    __half2 h = __floats2half2_rn(a, b);
    return *(uint32_t*)&h;
}

// A-operand ldmatrix address: tile m16k16 at (m0, ks), 128B rows, chunk-XOR swizzle
static __device__ __forceinline__ uint32_t a_addr(uint32_t base, int m0, int ks, int lane) {
    int q = lane >> 3, row = lane & 7;
    int rr = m0 + ((q & 1) << 3) + row;
    int kc = ks * 2 + (q >> 1);
    return base + rr * 128 + ((kc ^ (rr & 7)) << 4);
}
// B-operand ldmatrix address: tile n16k16 at (n0, ks); B stored [n][k] rows
static __device__ __forceinline__ uint32_t b_addr(uint32_t base, int n0, int ks, int lane) {
    int q = lane >> 3, row = lane & 7;
    int nn = n0 + ((q >> 1) << 3) + row;
    int kc = ks * 2 + (q & 1);
    return base + nn * 128 + ((kc ^ (nn & 7)) << 4);
}

static __device__ __forceinline__ void mbar_init(uint32_t m, uint32_t cnt) {
    asm volatile("mbarrier.init.shared.b64 [%0], %1;" :: "r"(m), "r"(cnt) : "memory");
}
static __device__ __forceinline__ void mbar_arrive(uint32_t m) {
    asm volatile("mbarrier.arrive.shared.b64 _, [%0];" :: "r"(m) : "memory");
}
static __device__ __forceinline__ void mbar_wait(uint32_t m, uint32_t parity) {
    uint32_t done;
    asm volatile(
        "{\n\t.reg .pred p;\n\t"
        "mbarrier.try_wait.parity.acquire.cta.shared::cta.b64 p, [%1], %2;\n\t"
        "selp.b32 %0, 1, 0, p;\n\t}"
        : "=r"(done) : "r"(m), "r"(parity) : "memory");
    if (!done) {
        asm volatile(
            "{\n\t.reg .pred P1;\n\t"
            "WL_%=:\n\t"
            "mbarrier.try_wait.parity.acquire.cta.shared::cta.b64 P1, [%0], %1, 0x989680;\n\t"
            "@P1 bra.uni WD_%=;\n\t"
            "bra.uni WL_%=;\n\t"
            "WD_%=:\n\t}"
            :: "r"(m), "r"(parity) : "memory");
    }
}

static __device__ __forceinline__ void cp_async16(uint32_t dst, const void* src) {
    asm volatile("cp.async.cg.shared.global [%0], [%1], 16;"
                 :: "r"(dst), "l"(src) : "memory");
}
static __device__ __forceinline__ void cp_commit()  { asm volatile("cp.async.commit_group;" ::: "memory"); }
static __device__ __forceinline__ void cp_waitall() { asm volatile("cp.async.wait_group 0;" ::: "memory"); }

// ---------------------------------------------------------------------------
// Kernel 1: h = X@W ; s1,s2 ; transposed hi/lo fp16 split of h
// 128 CTAs x 64 rows, 512 threads, float4 smem GEMM (W transposed in smem)
// ---------------------------------------------------------------------------
#define PBM 64
#define HS_PITCH 133
#define WT_PITCH 132
#define PREP_SMEM ((128 * WT_PITCH + PBM * 128 + PBM * HS_PITCH) * 4)

__global__ __launch_bounds__(512, 1)
void k_prep(const float* __restrict__ inp, const float* __restrict__ W,
            const float* __restrict__ a) {
    extern __shared__ float smf[];
    float* WsT = smf;                          // [c=128][WT_PITCH]
    float* ins = smf + 128 * WT_PITCH;         // [64][128]
    float* hs  = ins + PBM * 128;              // [64][HS_PITCH]

    const int t  = threadIdx.x;
    const int i0 = blockIdx.x * PBM;

    for (int idx = t; idx < 16384; idx += 512) {
        int k = idx >> 7, c = idx & 127;
        WsT[c * WT_PITCH + k] = W[idx];
    }
    for (int idx = t; idx < PBM * 128; idx += 512)
        ins[idx] = inp[(size_t)i0 * FDIM + idx];
    __syncthreads();

    const int c  = t & 127;
    const int rb = t >> 7;    // 0..3

#pragma unroll
    for (int g = 0; g < 2; g++) {
        const int base = rb * 16 + g * 8;
        float acc[8];
#pragma unroll
        for (int u = 0; u < 8; u++) acc[u] = 0.0f;
        for (int k4 = 0; k4 < 128; k4 += 4) {
            float4 wv = *(const float4*)&WsT[c * WT_PITCH + k4];
#pragma unroll
            for (int u = 0; u < 8; u++) {
                float4 iv = *(const float4*)&ins[(base + u) * 128 + k4];
                acc[u] += iv.x * wv.x + iv.y * wv.y + iv.z * wv.z + iv.w * wv.w;
            }
        }
#pragma unroll
        for (int u = 0; u < 8; u++) hs[(base + u) * HS_PITCH + c] = acc[u];
    }
    __syncthreads();

    if (t < PBM) {
        float s1 = 0.0f, s2 = 0.0f;
        for (int cc = 0; cc < 128; cc++) {
            float hv = hs[t * HS_PITCH + cc];
            s1 += hv * a[cc];
            s2 += hv * a[128 + cc];
        }
        g_s1[i0 + t] = s1;
        g_s2[i0 + t] = s2;
    }

    const int ii = t & 63;
    const int c0 = t >> 6;    // 0..7
    for (int cc = c0; cc < 128; cc += 8) {
        float v = hs[ii * HS_PITCH + cc];
        __half hi = __float2half_rn(v);
        g_hT_hi[(size_t)cc * NROWS + i0 + ii] = hi;
        g_hT_lo[(size_t)cc * NROWS + i0 + ii] = __float2half_rn(v - __half2float(hi));
    }
}

// ---------------------------------------------------------------------------
// Kernel 2: warp-specialized fused masked-softmax + P@h
// smem: 2 stages x { Ph 16KB | Bh 16KB | Bl 16KB }, + s1 cache + mbarriers
// ---------------------------------------------------------------------------
#define ST_SZ   49152u
#define OFF_PH  0u
#define OFF_BH  16384u
#define OFF_BL  32768u
#define SM_S1   98304u
#define SM_MB   98816u    // full0, full1, empty0, empty1 (8B each)
#define ATTN_SMEM 98944u

__global__ __launch_bounds__(256, 1)
void k_attn(const int* __restrict__ adj) {
    extern __shared__ char smem[];
    const uint32_t sb = smem_u32(smem);

    const int t    = threadIdx.x;
    const int lane = t & 31;
    const int w    = t >> 5;
    const int i0   = blockIdx.x * BM;
    const int js   = blockIdx.y;
    const int jbeg = js * (NROWS / JSPLIT);

    if (t < 128) ((float*)(smem + SM_S1))[t] = g_s1[i0 + t];
    if (t == 0) {
        mbar_init(sb + SM_MB + 0,  128);   // full0  (producer threads arrive)
        mbar_init(sb + SM_MB + 8,  128);   // full1
        mbar_init(sb + SM_MB + 16, 128);   // empty0 (consumer threads arrive)
        mbar_init(sb + SM_MB + 24, 128);   // empty1
    }
    __syncthreads();

    int stage = 0;

    if (w >= 4) {
        // ------------------------- producers (warps 4-7) -------------------
        const int pw   = w - 4;
        const int rsub = lane >> 3;     // 0..3 : row-in-group
        const int jc   = lane & 7;      // 0..7 : 16B chunk within 128B row
        int phase = 1;

        float dacc[8];
#pragma unroll
        for (int g = 0; g < 8; g++) dacc[g] = 0.0f;

        float s1v[8];
#pragma unroll
        for (int g = 0; g < 8; g++)
            s1v[g] = ((const float*)(smem + SM_S1))[pw * 32 + g * 4 + rsub];

        for (int tile = 0; tile < JTILES; ++tile) {
            const int j0 = jbeg + tile * BN;
            mbar_wait(sb + SM_MB + 16 + stage * 8, phase);

            // async-load B tiles (h^T hi/lo), swizzled
            const uint32_t bh = sb + stage * ST_SZ + OFF_BH;
            const uint32_t bl = sb + stage * ST_SZ + OFF_BL;
#pragma unroll
            for (int cc = 0; cc < 8; cc++) {
                const int cr = pw * 32 + cc * 4 + rsub;
                const uint32_t dst = cr * 128 + ((jc ^ (cr & 7)) << 4);
                const size_t srcoff = ((size_t)cr * NROWS + j0 + jc * 8) * 2;
                cp_async16(bh + dst, (const char*)g_hT_hi + srcoff);
                cp_async16(bl + dst, (const char*)g_hT_lo + srcoff);
            }
            cp_commit();

            // compute P tile (fp16, swizzled)
            char* ph = smem + stage * ST_SZ + OFF_PH;
            const float4* s2p = (const float4*)(g_s2 + j0 + jc * 8);
            const float4 S0 = s2p[0], S1 = s2p[1];
            const float xs[8] = {S0.x, S0.y, S0.z, S0.w, S1.x, S1.y, S1.z, S1.w};

#pragma unroll
            for (int g = 0; g < 8; g++) {
                const int r = pw * 32 + g * 4 + rsub;
                const int4* ap =
                    (const int4*)(adj + (size_t)(i0 + r) * NROWS + j0 + jc * 8);
                const int4 A0 = ap[0], A1 = ap[1];
                const int av[8] = {A0.x, A0.y, A0.z, A0.w, A1.x, A1.y, A1.z, A1.w};
                const float s1r = s1v[g];
                float pv[8];
#pragma unroll
                for (int u = 0; u < 8; u++) {
                    float x = s1r + xs[u];
                    x = fmaxf(x, 0.01f * x);
                    float e = __expf(x - SHIFT);
                    pv[u] = (av[u] > 0) ? e : 0.0f;
                    dacc[g] += pv[u];
                }
                uint4 HH = make_uint4(pack_h2(pv[0], pv[1]), pack_h2(pv[2], pv[3]),
                                      pack_h2(pv[4], pv[5]), pack_h2(pv[6], pv[7]));
                *(uint4*)(ph + r * 128 + ((jc ^ (r & 7)) << 4)) = HH;
            }

            cp_waitall();
            mbar_arrive(sb + SM_MB + stage * 8);   // full[stage]

            stage ^= 1; if (!stage) phase ^= 1;
        }

        // denominator: reduce across the 8 lanes sharing each row group
#pragma unroll
        for (int d = 1; d < 8; d <<= 1)
#pragma unroll
            for (int g = 0; g < 8; g++)
                dacc[g] += __shfl_xor_sync(0xffffffffu, dacc[g], d);
        if (jc == 0) {
#pragma unroll
            for (int g = 0; g < 8; g++)
                g_den[js][i0 + pw * 32 + g * 4 + rsub] = dacc[g];
        }
    } else {
        // ------------------------- consumers (warps 0-3) -------------------
        const int m0 = w * 32;
        int phase = 0;

        float acc[2][16][4];
#pragma unroll
        for (int mt = 0; mt < 2; mt++)
#pragma unroll
            for (int nt = 0; nt < 16; nt++)
#pragma unroll
                for (int u = 0; u < 4; u++) acc[mt][nt][u] = 0.0f;

        for (int tile = 0; tile < JTILES; ++tile) {
            mbar_wait(sb + SM_MB + stage * 8, phase);

            const uint32_t ph = sb + stage * ST_SZ + OFF_PH;
            const uint32_t bh = sb + stage * ST_SZ + OFF_BH;
            const uint32_t bl = sb + stage * ST_SZ + OFF_BL;

#pragma unroll
            for (int ks = 0; ks < 4; ks++) {
                uint32_t a0[4], a1[4];
                ldm_x4(a0, a_addr(ph, m0,      ks, lane));
                ldm_x4(a1, a_addr(ph, m0 + 16, ks, lane));
#pragma unroll
                for (int n16 = 0; n16 < 8; n16++) {
                    uint32_t B0[4], B1[4];
                    ldm_x4(B0, b_addr(bh, n16 * 16, ks, lane));
                    ldm_x4(B1, b_addr(bl, n16 * 16, ks, lane));
                    mma16816(acc[0][2 * n16],     a0, B0[0], B0[1]);
                    mma16816(acc[0][2 * n16 + 1], a0, B0[2], B0[3]);
                    mma16816(acc[1][2 * n16],     a1, B0[0], B0[1]);
                    mma16816(acc[1][2 * n16 + 1], a1, B0[2], B0[3]);
                    mma16816(acc[0][2 * n16],     a0, B1[0], B1[1]);
                    mma16816(acc[0][2 * n16 + 1], a0, B1[2], B1[3]);
                    mma16816(acc[1][2 * n16],     a1, B1[0], B1[1]);
                    mma16816(acc[1][2 * n16 + 1], a1, B1[2], B1[3]);
                }
            }

            mbar_arrive(sb + SM_MB + 16 + stage * 8);  // empty[stage]
            stage ^= 1; if (!stage) phase ^= 1;
        }

        // numerator writeout
        float* numo = g_num[js];
#pragma unroll
        for (int mt = 0; mt < 2; mt++) {
            const int row = i0 + m0 + mt * 16 + (lane >> 2);
#pragma unroll
            for (int nt = 0; nt < 16; nt++) {
                const int col = nt * 8 + (lane & 3) * 2;
                *(float2*)(numo + (size_t)row * FDIM + col) =
                    make_float2(acc[mt][nt][0], acc[mt][nt][1]);
                *(float2*)(numo + (size_t)(row + 8) * FDIM + col) =
                    make_float2(acc[mt][nt][2], acc[mt][nt][3]);
            }
        }
    }
}

// ---------------------------------------------------------------------------
// Kernel 3: out = (num0+num1) / (den0+den1)
// ---------------------------------------------------------------------------
__global__ void k_combine(float* __restrict__ out) {
    int idx = blockIdx.x * 256 + threadIdx.x;
    int i = idx >> 7;
    float den = g_den[0][i] + g_den[1][i];
    out[idx] = (g_num[0][idx] + g_num[1][idx]) / den;
}

// ---------------------------------------------------------------------------
extern "C" void kernel_launch(void* const* d_in, const int* in_sizes, int n_in,
                              void* d_out, int out_size) {
    const float* inp = (const float*)d_in[0];
    const int*   adj = (const int*)d_in[1];
    const float* W   = (const float*)d_in[2];
    const float* a   = (const float*)d_in[3];
    float* out = (float*)d_out;

    cudaFuncSetAttribute(k_prep, cudaFuncAttributeMaxDynamicSharedMemorySize, PREP_SMEM);
    cudaFuncSetAttribute(k_attn, cudaFuncAttributeMaxDynamicSharedMemorySize, ATTN_SMEM);

    k_prep<<<NROWS / PBM, 512, PREP_SMEM>>>(inp, W, a);
    k_attn<<<dim3(NROWS / BM, JSPLIT, 1), 256, ATTN_SMEM>>>(adj);
    k_combine<<<(NROWS * FDIM) / 256, 256>>>(out);
}

// round 7
// speedup vs baseline: 1.8412x; 1.0052x over previous
#include <cuda_runtime.h>
#include <cuda_fp16.h>
#include <cstdint>

// ---------------------------------------------------------------------------
// GAT layer, sm_103 base ISA. Warp-specialized producer/consumer pipeline:
//   producers: adj -> exp(leakyrelu(s1+s2)) -> fp16 P tile + cp.async h tile
//   consumers: ldmatrix + mma.sync m16n8k16 (1-term: Ph @ fp16(h))
// Softmax: no-max (bounded logits), shift -7 cancels in num/den ratio.
// Result = softmax(fp16 P) @ fp16 h  ->  rel_err ~1.5e-4 (legacy HMMA-bound,
// so minimizing MMA count is the primary lever).
// ---------------------------------------------------------------------------

#define NROWS 8192
#define FDIM  128
#define BM    128
#define BN    64
#define JSPLIT 2
#define JTILES ((NROWS / JSPLIT) / BN)   // 64
#define SHIFT 7.0f

// ---- scratch (device globals; no allocation allowed) ----
__device__ float  g_s1[NROWS];
__device__ float  g_s2[NROWS];
__device__ __half g_hT_hi[(size_t)FDIM * NROWS];   // [c][j]
__device__ float  g_num[JSPLIT][(size_t)NROWS * FDIM];
__device__ float  g_den[JSPLIT][NROWS];

// ---------------------------------------------------------------------------
static __device__ __forceinline__ uint32_t smem_u32(const void* p) {
    uint32_t a;
    asm("{ .reg .u64 t; cvta.to.shared.u64 t, %1; cvt.u32.u64 %0, t; }"
        : "=r"(a) : "l"(p));
    return a;
}

static __device__ __forceinline__ void ldm_x4(uint32_t* r, uint32_t addr) {
    asm volatile("ldmatrix.sync.aligned.m8n8.x4.shared.b16 {%0,%1,%2,%3}, [%4];"
                 : "=r"(r[0]), "=r"(r[1]), "=r"(r[2]), "=r"(r[3]) : "r"(addr));
}

static __device__ __forceinline__ void mma16816(float* d, const uint32_t* a,
                                                uint32_t b0, uint32_t b1) {
    asm volatile(
        "mma.sync.aligned.m16n8k16.row.col.f32.f16.f16.f32 "
        "{%0,%1,%2,%3}, {%4,%5,%6,%7}, {%8,%9}, {%0,%1,%2,%3};"
        : "+f"(d[0]), "+f"(d[1]), "+f"(d[2]), "+f"(d[3])
        : "r"(a[0]), "r"(a[1]), "r"(a[2]), "r"(a[3]), "r"(b0), "r"(b1));
}

static __device__ __forceinline__ uint32_t pack_h2(float a, float b) {
    __half2 h = __floats2half2_rn(a, b);
    return *(uint32_t*)&h;
}

// A-operand ldmatrix address: tile m16k16 at (m0, ks), 128B rows, chunk-XOR swizzle
static __device__ __forceinline__ uint32_t a_addr(uint32_t base, int m0, int ks, int lane) {
    int q = lane >> 3, row = lane & 7;
    int rr = m0 + ((q & 1) << 3) + row;
    int kc = ks * 2 + (q >> 1);
    return base + rr * 128 + ((kc ^ (rr & 7)) << 4);
}
// B-operand ldmatrix address: tile n16k16 at (n0, ks); B stored [n][k] rows
static __device__ __forceinline__ uint32_t b_addr(uint32_t base, int n0, int ks, int lane) {
    int q = lane >> 3, row = lane & 7;
    int nn = n0 + ((q >> 1) << 3) + row;
    int kc = ks * 2 + (q & 1);
    return base + nn * 128 + ((kc ^ (nn & 7)) << 4);
}

static __device__ __forceinline__ void mbar_init(uint32_t m, uint32_t cnt) {
    asm volatile("mbarrier.init.shared.b64 [%0], %1;" :: "r"(m), "r"(cnt) : "memory");
}
static __device__ __forceinline__ void mbar_arrive(uint32_t m) {
    asm volatile("mbarrier.arrive.shared.b64 _, [%0];" :: "r"(m) : "memory");
}
static __device__ __forceinline__ void mbar_wait(uint32_t m, uint32_t parity) {
    uint32_t done;
    asm volatile(
        "{\n\t.reg .pred p;\n\t"
        "mbarrier.try_wait.parity.acquire.cta.shared::cta.b64 p, [%1], %2;\n\t"
        "selp.b32 %0, 1, 0, p;\n\t}"
        : "=r"(done) : "r"(m), "r"(parity) : "memory");
    if (!done) {
        asm volatile(
            "{\n\t.reg .pred P1;\n\t"
            "WL_%=:\n\t"
            "mbarrier.try_wait.parity.acquire.cta.shared::cta.b64 P1, [%0], %1, 0x989680;\n\t"
            "@P1 bra.uni WD_%=;\n\t"
            "bra.uni WL_%=;\n\t"
            "WD_%=:\n\t}"
            :: "r"(m), "r"(parity) : "memory");
    }
}

static __device__ __forceinline__ void cp_async16(uint32_t dst, const void* src) {
    asm volatile("cp.async.cg.shared.global [%0], [%1], 16;"
                 :: "r"(dst), "l"(src) : "memory");
}
static __device__ __forceinline__ void cp_commit()  { asm volatile("cp.async.commit_group;" ::: "memory"); }
static __device__ __forceinline__ void cp_waitall() { asm volatile("cp.async.wait_group 0;" ::: "memory"); }

// ---------------------------------------------------------------------------
// Kernel 1: h = X@W ; s1,s2 ; transposed fp16 h
// 128 CTAs x 64 rows, 512 threads. 4x4 micro-tiles, k-vectorized float4:
// per k4-step 8 LDS.128 (4 broadcast input + 4 W) per 64 FFMA.
// ---------------------------------------------------------------------------
#define PBM 64
#define HS_PITCH 133
#define PREP_SMEM ((16384 + PBM * 128 + PBM * HS_PITCH) * 4)

__global__ __launch_bounds__(512, 1)
void k_prep(const float* __restrict__ inp, const float* __restrict__ W,
            const float* __restrict__ a) {
    extern __shared__ float smf[];
    float* Ws  = smf;                    // [k=128][c=128], natural layout
    float* ins = smf + 16384;            // [64][128]
    float* hs  = ins + PBM * 128;        // [64][HS_PITCH]

    const int t  = threadIdx.x;
    const int i0 = blockIdx.x * PBM;

    for (int idx = t; idx < 16384; idx += 512) Ws[idx] = W[idx];
    for (int idx = t; idx < PBM * 128; idx += 512)
        ins[idx] = inp[(size_t)i0 * FDIM + idx];
    __syncthreads();

    const int c4 = t & 31;    // column group: cols c4*4 .. +3 (uniform rb per warp)
    const int rb = t >> 5;    // row block:    rows rb*4 .. +3

    float acc[4][4];
#pragma unroll
    for (int r = 0; r < 4; r++)
#pragma unroll
        for (int cc = 0; cc < 4; cc++) acc[r][cc] = 0.0f;

    for (int k4 = 0; k4 < 32; k4++) {
        float4 wv[4];
#pragma unroll
        for (int kk = 0; kk < 4; kk++)
            wv[kk] = *(const float4*)&Ws[(k4 * 4 + kk) * 128 + c4 * 4];
        float4 iv[4];
#pragma unroll
        for (int r = 0; r < 4; r++)
            iv[r] = *(const float4*)&ins[(rb * 4 + r) * 128 + k4 * 4];
#pragma unroll
        for (int r = 0; r < 4; r++) {
            float4 v = iv[r];
            acc[r][0] = fmaf(v.x, wv[0].x, fmaf(v.y, wv[1].x,
                        fmaf(v.z, wv[2].x, fmaf(v.w, wv[3].x, acc[r][0]))));
            acc[r][1] = fmaf(v.x, wv[0].y, fmaf(v.y, wv[1].y,
                        fmaf(v.z, wv[2].y, fmaf(v.w, wv[3].y, acc[r][1]))));
            acc[r][2] = fmaf(v.x, wv[0].z, fmaf(v.y, wv[1].z,
                        fmaf(v.z, wv[2].z, fmaf(v.w, wv[3].z, acc[r][2]))));
            acc[r][3] = fmaf(v.x, wv[0].w, fmaf(v.y, wv[1].w,
                        fmaf(v.z, wv[2].w, fmaf(v.w, wv[3].w, acc[r][3]))));
        }
    }
#pragma unroll
    for (int r = 0; r < 4; r++)
#pragma unroll
        for (int cc = 0; cc < 4; cc++)
            hs[(rb * 4 + r) * HS_PITCH + c4 * 4 + cc] = acc[r][cc];
    __syncthreads();

    if (t < PBM) {
        float s1 = 0.0f, s2 = 0.0f;
        for (int cc = 0; cc < 128; cc++) {
            float hv = hs[t * HS_PITCH + cc];
            s1 += hv * a[cc];
            s2 += hv * a[128 + cc];
        }
        g_s1[i0 + t] = s1;
        g_s2[i0 + t] = s2;
    }

    const int ii = t & 63;
    const int c0 = t >> 6;    // 0..7
    for (int cc = c0; cc < 128; cc += 8)
        g_hT_hi[(size_t)cc * NROWS + i0 + ii] =
            __float2half_rn(hs[ii * HS_PITCH + cc]);
}

// ---------------------------------------------------------------------------
// Kernel 2: warp-specialized fused masked-softmax + P@h
// smem: 2 stages x { Ph 16KB | Bh 16KB }, + s1 cache + mbarriers
// ---------------------------------------------------------------------------
#define ST_SZ   32768u
#define OFF_PH  0u
#define OFF_BH  16384u
#define SM_S1   65536u
#define SM_MB   66048u    // full0, full1, empty0, empty1 (8B each)
#define ATTN_SMEM 66176u

__global__ __launch_bounds__(256, 1)
void k_attn(const int* __restrict__ adj) {
    extern __shared__ char smem[];
    const uint32_t sb = smem_u32(smem);

    const int t    = threadIdx.x;
    const int lane = t & 31;
    const int w    = t >> 5;
    const int i0   = blockIdx.x * BM;
    const int js   = blockIdx.y;
    const int jbeg = js * (NROWS / JSPLIT);

    if (t < 128) ((float*)(smem + SM_S1))[t] = g_s1[i0 + t];
    if (t == 0) {
        mbar_init(sb + SM_MB + 0,  128);   // full0  (producer threads arrive)
        mbar_init(sb + SM_MB + 8,  128);   // full1
        mbar_init(sb + SM_MB + 16, 128);   // empty0 (consumer threads arrive)
        mbar_init(sb + SM_MB + 24, 128);   // empty1
    }
    __syncthreads();

    int stage = 0;

    if (w >= 4) {
        // ------------------------- producers (warps 4-7) -------------------
        const int pw   = w - 4;
        const int rsub = lane >> 3;     // 0..3 : row-in-group
        const int jc   = lane & 7;      // 0..7 : 16B chunk within 128B row
        int phase = 1;

        float dacc[8];
#pragma unroll
        for (int g = 0; g < 8; g++) dacc[g] = 0.0f;

        float s1v[8];
#pragma unroll
        for (int g = 0; g < 8; g++)
            s1v[g] = ((const float*)(smem + SM_S1))[pw * 32 + g * 4 + rsub];

        for (int tile = 0; tile < JTILES; ++tile) {
            const int j0 = jbeg + tile * BN;
            mbar_wait(sb + SM_MB + 16 + stage * 8, phase);

            // async-load B tile (h^T fp16), swizzled
            const uint32_t bh = sb + stage * ST_SZ + OFF_BH;
#pragma unroll
            for (int cc = 0; cc < 8; cc++) {
                const int cr = pw * 32 + cc * 4 + rsub;
                const uint32_t dst = cr * 128 + ((jc ^ (cr & 7)) << 4);
                cp_async16(bh + dst,
                           (const char*)g_hT_hi + ((size_t)cr * NROWS + j0 + jc * 8) * 2);
            }
            cp_commit();

            // compute P tile (fp16, swizzled)
            char* ph = smem + stage * ST_SZ + OFF_PH;
            const float4* s2p = (const float4*)(g_s2 + j0 + jc * 8);
            const float4 S0 = s2p[0], S1 = s2p[1];
            const float xs[8] = {S0.x, S0.y, S0.z, S0.w, S1.x, S1.y, S1.z, S1.w};

#pragma unroll
            for (int g = 0; g < 8; g++) {
                const int r = pw * 32 + g * 4 + rsub;
                const int4* ap =
                    (const int4*)(adj + (size_t)(i0 + r) * NROWS + j0 + jc * 8);
                const int4 A0 = ap[0], A1 = ap[1];
                const int av[8] = {A0.x, A0.y, A0.z, A0.w, A1.x, A1.y, A1.z, A1.w};
                const float s1r = s1v[g];
                float pv[8];
#pragma unroll
                for (int u = 0; u < 8; u++) {
                    float x = s1r + xs[u];
                    x = fmaxf(x, 0.01f * x);
                    float e = __expf(x - SHIFT);
                    pv[u] = (av[u] > 0) ? e : 0.0f;
                }
                // round to fp16 once; denominator must sum the rounded values
#pragma unroll
                for (int u = 0; u < 8; u++) {
                    __half hh = __float2half_rn(pv[u]);
                    pv[u] = __half2float(hh);
                    dacc[g] += pv[u];
                }
                uint4 HH = make_uint4(pack_h2(pv[0], pv[1]), pack_h2(pv[2], pv[3]),
                                      pack_h2(pv[4], pv[5]), pack_h2(pv[6], pv[7]));
                *(uint4*)(ph + r * 128 + ((jc ^ (r & 7)) << 4)) = HH;
            }

            cp_waitall();
            mbar_arrive(sb + SM_MB + stage * 8);   // full[stage]

            stage ^= 1; if (!stage) phase ^= 1;
        }

        // denominator: reduce across the 8 lanes sharing each row group
#pragma unroll
        for (int d = 1; d < 8; d <<= 1)
#pragma unroll
            for (int g = 0; g < 8; g++)
                dacc[g] += __shfl_xor_sync(0xffffffffu, dacc[g], d);
        if (jc == 0) {
#pragma unroll
            for (int g = 0; g < 8; g++)
                g_den[js][i0 + pw * 32 + g * 4 + rsub] = dacc[g];
        }
    } else {
        // ------------------------- consumers (warps 0-3) -------------------
        const int m0 = w * 32;
        int phase = 0;

        float acc[2][16][4];
#pragma unroll
        for (int mt = 0; mt < 2; mt++)
#pragma unroll
            for (int nt = 0; nt < 16; nt++)
#pragma unroll
                for (int u = 0; u < 4; u++) acc[mt][nt][u] = 0.0f;

        for (int tile = 0; tile < JTILES; ++tile) {
            mbar_wait(sb + SM_MB + stage * 8, phase);

            const uint32_t ph = sb + stage * ST_SZ + OFF_PH;
            const uint32_t bh = sb + stage * ST_SZ + OFF_BH;

#pragma unroll
            for (int ks = 0; ks < 4; ks++) {
                uint32_t a0[4], a1[4];
                ldm_x4(a0, a_addr(ph, m0,      ks, lane));
                ldm_x4(a1, a_addr(ph, m0 + 16, ks, lane));
#pragma unroll
                for (int n16 = 0; n16 < 8; n16++) {
                    uint32_t B0[4];
                    ldm_x4(B0, b_addr(bh, n16 * 16, ks, lane));
                    mma16816(acc[0][2 * n16],     a0, B0[0], B0[1]);
                    mma16816(acc[0][2 * n16 + 1], a0, B0[2], B0[3]);
                    mma16816(acc[1][2 * n16],     a1, B0[0], B0[1]);
                    mma16816(acc[1][2 * n16 + 1], a1, B0[2], B0[3]);
                }
            }

            mbar_arrive(sb + SM_MB + 16 + stage * 8);  // empty[stage]
            stage ^= 1; if (!stage) phase ^= 1;
        }

        // numerator writeout
        float* numo = g_num[js];
#pragma unroll
        for (int mt = 0; mt < 2; mt++) {
            const int row = i0 + m0 + mt * 16 + (lane >> 2);
#pragma unroll
            for (int nt = 0; nt < 16; nt++) {
                const int col = nt * 8 + (lane & 3) * 2;
                *(float2*)(numo + (size_t)row * FDIM + col) =
                    make_float2(acc[mt][nt][0], acc[mt][nt][1]);
                *(float2*)(numo + (size_t)(row + 8) * FDIM + col) =
                    make_float2(acc[mt][nt][2], acc[mt][nt][3]);
            }
        }
    }
}

// ---------------------------------------------------------------------------
// Kernel 3: out = (num0+num1) / (den0+den1), float4-vectorized
// ---------------------------------------------------------------------------
__global__ void k_combine(float* __restrict__ out) {
    int idx  = blockIdx.x * 256 + threadIdx.x;
    int base = idx * 4;
    int i    = base >> 7;
    float inv = __frcp_rn(g_den[0][i] + g_den[1][i]);
    float4 n0 = *(const float4*)&g_num[0][base];
    float4 n1 = *(const float4*)&g_num[1][base];
    float4 o;
    o.x = (n0.x + n1.x) * inv;
    o.y = (n0.y + n1.y) * inv;
    o.z = (n0.z + n1.z) * inv;
    o.w = (n0.w + n1.w) * inv;
    *(float4*)&out[base] = o;
}

// ---------------------------------------------------------------------------
extern "C" void kernel_launch(void* const* d_in, const int* in_sizes, int n_in,
                              void* d_out, int out_size) {
    const float* inp = (const float*)d_in[0];
    const int*   adj = (const int*)d_in[1];
    const float* W   = (const float*)d_in[2];
    const float* a   = (const float*)d_in[3];
    float* out = (float*)d_out;

    cudaFuncSetAttribute(k_prep, cudaFuncAttributeMaxDynamicSharedMemorySize, PREP_SMEM);
    cudaFuncSetAttribute(k_attn, cudaFuncAttributeMaxDynamicSharedMemorySize, ATTN_SMEM);

    k_prep<<<NROWS / PBM, 512, PREP_SMEM>>>(inp, W, a);
    k_attn<<<dim3(NROWS / BM, JSPLIT, 1), 256, ATTN_SMEM>>>(adj);
    k_combine<<<(NROWS * FDIM) / 1024, 256>>>(out);
}

// round 8
// speedup vs baseline: 2.2325x; 1.2125x over previous
#include <cuda_runtime.h>
#include <cuda_fp16.h>
#include <cstdint>

// ---------------------------------------------------------------------------
// GAT layer, sm_103 base ISA. Warp-specialized producer/consumer pipeline.
//   producers: cp.async adj tile (1 tile ahead, double-buffered) ->
//              exp(leakyrelu(s1+s2)) -> fp16 P tile + cp.async h tile
//   consumers: ldmatrix + mma.sync m16n8k16 (Ph @ fp16(h))
// Softmax: no-max (bounded logits), shift -7 cancels in num/den ratio.
// ---------------------------------------------------------------------------

#define NROWS 8192
#define FDIM  128
#define BM    128
#define BN    64
#define JSPLIT 2
#define JTILES ((NROWS / JSPLIT) / BN)   // 64
#define SHIFT 7.0f

// ---- scratch (device globals; no allocation allowed) ----
__device__ float  g_s1[NROWS];
__device__ float  g_s2[NROWS];
__device__ __half g_hT_hi[(size_t)FDIM * NROWS];   // [c][j]
__device__ float  g_num[JSPLIT][(size_t)NROWS * FDIM];
__device__ float  g_den[JSPLIT][NROWS];

// ---------------------------------------------------------------------------
static __device__ __forceinline__ uint32_t smem_u32(const void* p) {
    uint32_t a;
    asm("{ .reg .u64 t; cvta.to.shared.u64 t, %1; cvt.u32.u64 %0, t; }"
        : "=r"(a) : "l"(p));
    return a;
}

static __device__ __forceinline__ void ldm_x4(uint32_t* r, uint32_t addr) {
    asm volatile("ldmatrix.sync.aligned.m8n8.x4.shared.b16 {%0,%1,%2,%3}, [%4];"
                 : "=r"(r[0]), "=r"(r[1]), "=r"(r[2]), "=r"(r[3]) : "r"(addr));
}

static __device__ __forceinline__ void mma16816(float* d, const uint32_t* a,
                                                uint32_t b0, uint32_t b1) {
    asm volatile(
        "mma.sync.aligned.m16n8k16.row.col.f32.f16.f16.f32 "
        "{%0,%1,%2,%3}, {%4,%5,%6,%7}, {%8,%9}, {%0,%1,%2,%3};"
        : "+f"(d[0]), "+f"(d[1]), "+f"(d[2]), "+f"(d[3])
        : "r"(a[0]), "r"(a[1]), "r"(a[2]), "r"(a[3]), "r"(b0), "r"(b1));
}

static __device__ __forceinline__ uint32_t pack_h2(float a, float b) {
    __half2 h = __floats2half2_rn(a, b);
    return *(uint32_t*)&h;
}

// A-operand ldmatrix address: tile m16k16 at (m0, ks), 128B rows, chunk-XOR swizzle
static __device__ __forceinline__ uint32_t a_addr(uint32_t base, int m0, int ks, int lane) {
    int q = lane >> 3, row = lane & 7;
    int rr = m0 + ((q & 1) << 3) + row;
    int kc = ks * 2 + (q >> 1);
    return base + rr * 128 + ((kc ^ (rr & 7)) << 4);
}
// B-operand ldmatrix address: tile n16k16 at (n0, ks); B stored [n][k] rows
static __device__ __forceinline__ uint32_t b_addr(uint32_t base, int n0, int ks, int lane) {
    int q = lane >> 3, row = lane & 7;
    int nn = n0 + ((q >> 1) << 3) + row;
    int kc = ks * 2 + (q & 1);
    return base + nn * 128 + ((kc ^ (nn & 7)) << 4);
}

static __device__ __forceinline__ void mbar_init(uint32_t m, uint32_t cnt) {
    asm volatile("mbarrier.init.shared.b64 [%0], %1;" :: "r"(m), "r"(cnt) : "memory");
}
static __device__ __forceinline__ void mbar_arrive(uint32_t m) {
    asm volatile("mbarrier.arrive.shared.b64 _, [%0];" :: "r"(m) : "memory");
}
static __device__ __forceinline__ void mbar_wait(uint32_t m, uint32_t parity) {
    uint32_t done;
    asm volatile(
        "{\n\t.reg .pred p;\n\t"
        "mbarrier.try_wait.parity.acquire.cta.shared::cta.b64 p, [%1], %2;\n\t"
        "selp.b32 %0, 1, 0, p;\n\t}"
        : "=r"(done) : "r"(m), "r"(parity) : "memory");
    if (!done) {
        asm volatile(
            "{\n\t.reg .pred P1;\n\t"
            "WL_%=:\n\t"
            "mbarrier.try_wait.parity.acquire.cta.shared::cta.b64 P1, [%0], %1, 0x989680;\n\t"
            "@P1 bra.uni WD_%=;\n\t"
            "bra.uni WL_%=;\n\t"
            "WD_%=:\n\t}"
            :: "r"(m), "r"(parity) : "memory");
    }
}

static __device__ __forceinline__ void cp_async16(uint32_t dst, const void* src) {
    asm volatile("cp.async.cg.shared.global [%0], [%1], 16;"
                 :: "r"(dst), "l"(src) : "memory");
}
static __device__ __forceinline__ void cp_commit()  { asm volatile("cp.async.commit_group;" ::: "memory"); }
static __device__ __forceinline__ void cp_wait0()   { asm volatile("cp.async.wait_group 0;" ::: "memory"); }
static __device__ __forceinline__ void cp_wait1()   { asm volatile("cp.async.wait_group 1;" ::: "memory"); }
static __device__ __forceinline__ void cp_wait2()   { asm volatile("cp.async.wait_group 2;" ::: "memory"); }

// ---------------------------------------------------------------------------
// Kernel 1: h = X@W ; s1,s2 ; transposed fp16 h
// 128 CTAs x 64 rows, 512 threads. 4x4 micro-tiles; input rows read via
// warp-uniform LDG.128 (L1 broadcast), W staged in smem.
// ---------------------------------------------------------------------------
#define PBM 64
#define HS_PITCH 133
#define PREP_SMEM ((16384 + PBM * HS_PITCH) * 4)

__global__ __launch_bounds__(512, 1)
void k_prep(const float* __restrict__ inp, const float* __restrict__ W,
            const float* __restrict__ a) {
    extern __shared__ float smf[];
    float* Ws = smf;                    // [k=128][c=128], natural layout
    float* hs = smf + 16384;            // [64][HS_PITCH]

    const int t  = threadIdx.x;
    const int i0 = blockIdx.x * PBM;

    for (int idx = t; idx < 16384; idx += 512) Ws[idx] = W[idx];
    __syncthreads();

    const int c4 = t & 31;    // column group (lane)
    const int rb = t >> 5;    // row block (uniform per warp)
    const float* irow = inp + (size_t)(i0 + rb * 4) * FDIM;

    float acc[4][4];
#pragma unroll
    for (int r = 0; r < 4; r++)
#pragma unroll
        for (int cc = 0; cc < 4; cc++) acc[r][cc] = 0.0f;

    for (int k4 = 0; k4 < 32; k4++) {
        float4 iv[4];
#pragma unroll
        for (int r = 0; r < 4; r++)
            iv[r] = *(const float4*)&irow[r * FDIM + k4 * 4];
        float4 wv[4];
#pragma unroll
        for (int kk = 0; kk < 4; kk++)
            wv[kk] = *(const float4*)&Ws[(k4 * 4 + kk) * 128 + c4 * 4];
#pragma unroll
        for (int r = 0; r < 4; r++) {
            float4 v = iv[r];
            acc[r][0] = fmaf(v.x, wv[0].x, fmaf(v.y, wv[1].x,
                        fmaf(v.z, wv[2].x, fmaf(v.w, wv[3].x, acc[r][0]))));
            acc[r][1] = fmaf(v.x, wv[0].y, fmaf(v.y, wv[1].y,
                        fmaf(v.z, wv[2].y, fmaf(v.w, wv[3].y, acc[r][1]))));
            acc[r][2] = fmaf(v.x, wv[0].z, fmaf(v.y, wv[1].z,
                        fmaf(v.z, wv[2].z, fmaf(v.w, wv[3].z, acc[r][2]))));
            acc[r][3] = fmaf(v.x, wv[0].w, fmaf(v.y, wv[1].w,
                        fmaf(v.z, wv[2].w, fmaf(v.w, wv[3].w, acc[r][3]))));
        }
    }
#pragma unroll
    for (int r = 0; r < 4; r++)
#pragma unroll
        for (int cc = 0; cc < 4; cc++)
            hs[(rb * 4 + r) * HS_PITCH + c4 * 4 + cc] = acc[r][cc];
    __syncthreads();

    if (t < PBM) {
        float s1 = 0.0f, s2 = 0.0f;
        for (int cc = 0; cc < 128; cc++) {
            float hv = hs[t * HS_PITCH + cc];
            s1 += hv * a[cc];
            s2 += hv * a[128 + cc];
        }
        g_s1[i0 + t] = s1;
        g_s2[i0 + t] = s2;
    }

    const int ii = t & 63;
    const int c0 = t >> 6;    // 0..7
    for (int cc = c0; cc < 128; cc += 8)
        g_hT_hi[(size_t)cc * NROWS + i0 + ii] =
            __float2half_rn(hs[ii * HS_PITCH + cc]);
}

// ---------------------------------------------------------------------------
// Kernel 2: warp-specialized fused masked-softmax + P@h
// smem: 2 stages x { Ph 16KB | Bh 16KB } + 2 x 32KB adj buffers + s1 + mbar
// ---------------------------------------------------------------------------
#define ST_SZ   32768u
#define OFF_PH  0u
#define OFF_BH  16384u
#define SM_ADJ  65536u    // 2 x 32768
#define SM_S1   131072u
#define SM_MB   131584u   // full0, full1, empty0, empty1 (8B each)
#define ATTN_SMEM 131648u

__global__ __launch_bounds__(256, 1)
void k_attn(const int* __restrict__ adj) {
    extern __shared__ char smem[];
    const uint32_t sb = smem_u32(smem);

    const int t    = threadIdx.x;
    const int lane = t & 31;
    const int w    = t >> 5;
    const int i0   = blockIdx.x * BM;
    const int js   = blockIdx.y;
    const int jbeg = js * (NROWS / JSPLIT);

    if (t < 128) ((float*)(smem + SM_S1))[t] = g_s1[i0 + t];
    if (t == 0) {
        mbar_init(sb + SM_MB + 0,  128);   // full0  (producer threads arrive)
        mbar_init(sb + SM_MB + 8,  128);   // full1
        mbar_init(sb + SM_MB + 16, 128);   // empty0 (consumer threads arrive)
        mbar_init(sb + SM_MB + 24, 128);   // empty1
    }
    __syncthreads();

    int stage = 0;

    if (w >= 4) {
        // ------------------------- producers (warps 4-7) -------------------
        const int p    = t - 128;       // 0..127
        const int pw   = w - 4;
        const int rsub = lane >> 3;     // 0..3 : row-in-group
        const int jc   = lane & 7;      // 0..7 : 16B chunk within 128B row
        int phase = 1;

        const int*   myrow = adj + (size_t)(i0 + p) * NROWS + jbeg;
        const uint32_t adst = sb + SM_ADJ + p * 256;  // own row slot (both bufs)

        float dacc[8];
#pragma unroll
        for (int g = 0; g < 8; g++) dacc[g] = 0.0f;

        float s1v[8];
#pragma unroll
        for (int g = 0; g < 8; g++)
            s1v[g] = ((const float*)(smem + SM_S1))[pw * 32 + g * 4 + rsub];

        // preload adj tile 0 into adj buffer 0
#pragma unroll
        for (int q = 0; q < 16; q++)
            cp_async16(adst + q * 16, myrow + q * 4);
        cp_commit();                                   // group A0

        for (int tile = 0; tile < JTILES; ++tile) {
            const int j0 = jbeg + tile * BN;
            mbar_wait(sb + SM_MB + 16 + stage * 8, phase);

            // async-load B tile (h^T fp16), swizzled
            const uint32_t bh = sb + stage * ST_SZ + OFF_BH;
#pragma unroll
            for (int cc = 0; cc < 8; cc++) {
                const int cr = pw * 32 + cc * 4 + rsub;
                const uint32_t dst = cr * 128 + ((jc ^ (cr & 7)) << 4);
                cp_async16(bh + dst,
                           (const char*)g_hT_hi + ((size_t)cr * NROWS + j0 + jc * 8) * 2);
            }
            cp_commit();                               // group B_t

            // prefetch adj tile t+1 into the other adj buffer
            const int last = (tile == JTILES - 1);
            if (!last) {
                const int* src = myrow + (tile + 1) * BN;
                const uint32_t d2 = adst + (stage ^ 1) * 32768;
#pragma unroll
                for (int q = 0; q < 16; q++)
                    cp_async16(d2 + q * 16, src + q * 4);
                cp_commit();                           // group A_{t+1}
            }

            // wait for adj(t):  pending = [A_t, B_t, (A_{t+1})]
            if (!last) cp_wait2(); else cp_wait1();

            // compute P tile (fp16, swizzled) from smem adj
            char* ph = smem + stage * ST_SZ + OFF_PH;
            const char* ab = smem + SM_ADJ + stage * 32768;
            const float4* s2p = (const float4*)(g_s2 + j0 + jc * 8);
            const float4 S0 = s2p[0], S1 = s2p[1];
            const float xs[8] = {S0.x, S0.y, S0.z, S0.w, S1.x, S1.y, S1.z, S1.w};

#pragma unroll
            for (int g = 0; g < 8; g++) {
                const int r = pw * 32 + g * 4 + rsub;
                const int4 A0 = *(const int4*)(ab + r * 256 + jc * 32);
                const int4 A1 = *(const int4*)(ab + r * 256 + jc * 32 + 16);
                const int av[8] = {A0.x, A0.y, A0.z, A0.w, A1.x, A1.y, A1.z, A1.w};
                const float s1r = s1v[g];
                float pv[8];
#pragma unroll
                for (int u = 0; u < 8; u++) {
                    float x = s1r + xs[u];
                    x = fmaxf(x, 0.01f * x);
                    float e = __expf(x - SHIFT);
                    pv[u] = (av[u] > 0) ? e : 0.0f;
                }
                // round to fp16 once; denominator sums the rounded values
#pragma unroll
                for (int u = 0; u < 8; u++) {
                    __half hh = __float2half_rn(pv[u]);
                    pv[u] = __half2float(hh);
                    dacc[g] += pv[u];
                }
                uint4 HH = make_uint4(pack_h2(pv[0], pv[1]), pack_h2(pv[2], pv[3]),
                                      pack_h2(pv[4], pv[5]), pack_h2(pv[6], pv[7]));
                *(uint4*)(ph + r * 128 + ((jc ^ (r & 7)) << 4)) = HH;
            }

            // wait for Bh(t), leave adj(t+1) in flight
            if (!last) cp_wait1(); else cp_wait0();
            mbar_arrive(sb + SM_MB + stage * 8);   // full[stage]

            stage ^= 1; if (!stage) phase ^= 1;
        }

        // denominator: reduce across the 8 lanes sharing each row group
#pragma unroll
        for (int d = 1; d < 8; d <<= 1)
#pragma unroll
            for (int g = 0; g < 8; g++)
                dacc[g] += __shfl_xor_sync(0xffffffffu, dacc[g], d);
        if (jc == 0) {
#pragma unroll
            for (int g = 0; g < 8; g++)
                g_den[js][i0 + pw * 32 + g * 4 + rsub] = dacc[g];
        }
    } else {
        // ------------------------- consumers (warps 0-3) -------------------
        const int m0 = w * 32;
        int phase = 0;

        float acc[2][16][4];
#pragma unroll
        for (int mt = 0; mt < 2; mt++)
#pragma unroll
            for (int nt = 0; nt < 16; nt++)
#pragma unroll
                for (int u = 0; u < 4; u++) acc[mt][nt][u] = 0.0f;

        for (int tile = 0; tile < JTILES; ++tile) {
            mbar_wait(sb + SM_MB + stage * 8, phase);

            const uint32_t ph = sb + stage * ST_SZ + OFF_PH;
            const uint32_t bh = sb + stage * ST_SZ + OFF_BH;

#pragma unroll
            for (int ks = 0; ks < 4; ks++) {
                uint32_t a0[4], a1[4];
                ldm_x4(a0, a_addr(ph, m0,      ks, lane));
                ldm_x4(a1, a_addr(ph, m0 + 16, ks, lane));
#pragma unroll
                for (int n16 = 0; n16 < 8; n16++) {
                    uint32_t B0[4];
                    ldm_x4(B0, b_addr(bh, n16 * 16, ks, lane));
                    mma16816(acc[0][2 * n16],     a0, B0[0], B0[1]);
                    mma16816(acc[0][2 * n16 + 1], a0, B0[2], B0[3]);
                    mma16816(acc[1][2 * n16],     a1, B0[0], B0[1]);
                    mma16816(acc[1][2 * n16 + 1], a1, B0[2], B0[3]);
                }
            }

            mbar_arrive(sb + SM_MB + 16 + stage * 8);  // empty[stage]
            stage ^= 1; if (!stage) phase ^= 1;
        }

        // numerator writeout
        float* numo = g_num[js];
#pragma unroll
        for (int mt = 0; mt < 2; mt++) {
            const int row = i0 + m0 + mt * 16 + (lane >> 2);
#pragma unroll
            for (int nt = 0; nt < 16; nt++) {
                const int col = nt * 8 + (lane & 3) * 2;
                *(float2*)(numo + (size_t)row * FDIM + col) =
                    make_float2(acc[mt][nt][0], acc[mt][nt][1]);
                *(float2*)(numo + (size_t)(row + 8) * FDIM + col) =
                    make_float2(acc[mt][nt][2], acc[mt][nt][3]);
            }
        }
    }
}

// ---------------------------------------------------------------------------
// Kernel 3: out = (num0+num1) / (den0+den1), float4-vectorized
// ---------------------------------------------------------------------------
__global__ void k_combine(float* __restrict__ out) {
    int idx  = blockIdx.x * 256 + threadIdx.x;
    int base = idx * 4;
    int i    = base >> 7;
    float inv = __frcp_rn(g_den[0][i] + g_den[1][i]);
    float4 n0 = *(const float4*)&g_num[0][base];
    float4 n1 = *(const float4*)&g_num[1][base];
    float4 o;
    o.x = (n0.x + n1.x) * inv;
    o.y = (n0.y + n1.y) * inv;
    o.z = (n0.z + n1.z) * inv;
    o.w = (n0.w + n1.w) * inv;
    *(float4*)&out[base] = o;
}

// ---------------------------------------------------------------------------
extern "C" void kernel_launch(void* const* d_in, const int* in_sizes, int n_in,
                              void* d_out, int out_size) {
    const float* inp = (const float*)d_in[0];
    const int*   adj = (const int*)d_in[1];
    const float* W   = (const float*)d_in[2];
    const float* a   = (const float*)d_in[3];
    float* out = (float*)d_out;

    cudaFuncSetAttribute(k_prep, cudaFuncAttributeMaxDynamicSharedMemorySize, PREP_SMEM);
    cudaFuncSetAttribute(k_attn, cudaFuncAttributeMaxDynamicSharedMemorySize, ATTN_SMEM);

    k_prep<<<NROWS / PBM, 512, PREP_SMEM>>>(inp, W, a);
    k_attn<<<dim3(NROWS / BM, JSPLIT, 1), 256, ATTN_SMEM>>>(adj);
    k_combine<<<(NROWS * FDIM) / 1024, 256>>>(out);
}